// round 1
// baseline (speedup 1.0000x reference)
#include <cuda_runtime.h>

constexpr int B_BATCH   = 4096;
constexpr int MAX_ATOMS = 2048;
constexpr int ROW       = 3 * MAX_ATOMS;   // 6144 floats per batch row
constexpr int THREADS   = 256;

__global__ __launch_bounds__(THREADS)
void kabsch_rmsd_kernel(const float* __restrict__ inp,
                        const float* __restrict__ tgt,
                        const int*   __restrict__ lens,
                        float*       __restrict__ out)
{
    const int b = blockIdx.x;
    const int n = lens[b] + 1;   // valid atoms: indices [0, n)
    const float4* __restrict__ x4 = reinterpret_cast<const float4*>(inp + (size_t)b * ROW);
    const float4* __restrict__ y4 = reinterpret_cast<const float4*>(tgt + (size_t)b * ROW);

    // acc layout: [0..2]=SX  [3..5]=SY  [6]=sum|x|^2  [7]=sum|y|^2  [8..16]=Sxy row-major
    float acc[17];
#pragma unroll
    for (int i = 0; i < 17; i++) acc[i] = 0.f;

    for (int a0 = threadIdx.x * 4; a0 < n; a0 += THREADS * 4) {
        const int f = 3 * (a0 >> 2);     // float4 index of this 4-atom (12-float) group
        float4 xa = x4[f], xb = x4[f + 1], xc = x4[f + 2];
        float4 ya = y4[f], yb = y4[f + 1], yc = y4[f + 2];
        float xs[12] = {xa.x, xa.y, xa.z, xa.w, xb.x, xb.y, xb.z, xb.w, xc.x, xc.y, xc.z, xc.w};
        float ys[12] = {ya.x, ya.y, ya.z, ya.w, yb.x, yb.y, yb.z, yb.w, yc.x, yc.y, yc.z, yc.w};
#pragma unroll
        for (int j = 0; j < 4; j++) {
            if (a0 + j < n) {
                float x0 = xs[3*j], x1 = xs[3*j+1], x2 = xs[3*j+2];
                float y0 = ys[3*j], y1 = ys[3*j+1], y2 = ys[3*j+2];
                acc[0] += x0; acc[1] += x1; acc[2] += x2;
                acc[3] += y0; acc[4] += y1; acc[5] += y2;
                acc[6]  = fmaf(x0, x0, fmaf(x1, x1, fmaf(x2, x2, acc[6])));
                acc[7]  = fmaf(y0, y0, fmaf(y1, y1, fmaf(y2, y2, acc[7])));
                acc[8]  = fmaf(x0, y0, acc[8]);
                acc[9]  = fmaf(x0, y1, acc[9]);
                acc[10] = fmaf(x0, y2, acc[10]);
                acc[11] = fmaf(x1, y0, acc[11]);
                acc[12] = fmaf(x1, y1, acc[12]);
                acc[13] = fmaf(x1, y2, acc[13]);
                acc[14] = fmaf(x2, y0, acc[14]);
                acc[15] = fmaf(x2, y1, acc[15]);
                acc[16] = fmaf(x2, y2, acc[16]);
            }
        }
    }

    // intra-warp tree reduction
#pragma unroll
    for (int i = 0; i < 17; i++) {
#pragma unroll
        for (int o = 16; o > 0; o >>= 1)
            acc[i] += __shfl_down_sync(0xffffffffu, acc[i], o);
    }

    __shared__ float red[THREADS / 32][17];
    const int warp = threadIdx.x >> 5;
    const int lane = threadIdx.x & 31;
    if (lane == 0) {
#pragma unroll
        for (int i = 0; i < 17; i++) red[warp][i] = acc[i];
    }
    __syncthreads();

    __shared__ float fin[17];
    if (threadIdx.x < 17) {
        float s = 0.f;
#pragma unroll
        for (int w = 0; w < THREADS / 32; w++) s += red[w][threadIdx.x];
        fin[threadIdx.x] = s;
    }
    __syncthreads();

    if (threadIdx.x == 0) {
        const double nd = (double)n;
        double SX[3] = {fin[0], fin[1], fin[2]};
        double SY[3] = {fin[3], fin[4], fin[5]};
        double sxx = fin[6], syy = fin[7];

        double C[3][3];
#pragma unroll
        for (int i = 0; i < 3; i++)
#pragma unroll
            for (int j = 0; j < 3; j++)
                C[i][j] = (double)fin[8 + 3*i + j] - SX[i] * SY[j] / nd;

        double ssq = sxx - (SX[0]*SX[0] + SX[1]*SX[1] + SX[2]*SX[2]) / nd
                   + syy - (SY[0]*SY[0] + SY[1]*SY[1] + SY[2]*SY[2]) / nd;

        // M = C^T C (symmetric PSD); eigenvalues -> singular values of C
        double M[3][3];
#pragma unroll
        for (int i = 0; i < 3; i++)
#pragma unroll
            for (int j = 0; j < 3; j++) {
                double s = 0.0;
#pragma unroll
                for (int k = 0; k < 3; k++) s += C[k][i] * C[k][j];
                M[i][j] = s;
            }

        double q  = (M[0][0] + M[1][1] + M[2][2]) / 3.0;
        double p1 = M[0][1]*M[0][1] + M[0][2]*M[0][2] + M[1][2]*M[1][2];
        double a  = M[0][0] - q, bb = M[1][1] - q, c = M[2][2] - q;
        double p2 = a*a + bb*bb + c*c + 2.0 * p1;

        double e0, e1, e2;
        if (p2 <= 0.0) {
            e0 = e1 = e2 = q;
        } else {
            double p   = sqrt(p2 / 6.0);
            double inv = 1.0 / p;
            double B00 = a * inv, B11 = bb * inv, B22 = c * inv;
            double B01 = M[0][1] * inv, B02 = M[0][2] * inv, B12 = M[1][2] * inv;
            double detB = B00 * (B11*B22 - B12*B12)
                        - B01 * (B01*B22 - B12*B02)
                        + B02 * (B01*B12 - B11*B02);
            double r = 0.5 * detB;
            r = fmin(1.0, fmax(-1.0, r));
            double phi = acos(r) / 3.0;
            e0 = q + 2.0 * p * cos(phi);                        // largest
            e2 = q + 2.0 * p * cos(phi + 2.0943951023931953);   // smallest (phi + 2pi/3)
            e1 = 3.0 * q - e0 - e2;                             // middle
        }

        double s0 = sqrt(fmax(e0, 0.0));
        double s1 = sqrt(fmax(e1, 0.0));
        double s2 = sqrt(fmax(e2, 0.0));

        double detC = C[0][0] * (C[1][1]*C[2][2] - C[1][2]*C[2][1])
                    - C[0][1] * (C[1][0]*C[2][2] - C[1][2]*C[2][0])
                    + C[0][2] * (C[1][0]*C[2][1] - C[1][1]*C[2][0]);
        double sgn = (detC > 0.0) ? 1.0 : ((detC < 0.0) ? -1.0 : 0.0);

        double tr  = s0 + s1 + sgn * s2;
        double msd = fmax(ssq - 2.0 * tr, 0.0) / nd;
        out[b] = (float)sqrt(msd + 1e-12);
    }
}

extern "C" void kernel_launch(void* const* d_in, const int* in_sizes, int n_in,
                              void* d_out, int out_size)
{
    const float* inp  = (const float*)d_in[0];
    const float* tgt  = (const float*)d_in[1];
    const int*   lens = (const int*)d_in[2];
    float*       out  = (float*)d_out;
    kabsch_rmsd_kernel<<<B_BATCH, THREADS>>>(inp, tgt, lens, out);
}

// round 2
// speedup vs baseline: 1.1098x; 1.1098x over previous
#include <cuda_runtime.h>

constexpr int B_BATCH   = 4096;
constexpr int MAX_ATOMS = 2048;
constexpr int ROW       = 3 * MAX_ATOMS;   // 6144 floats per batch row
constexpr int THREADS   = 256;             // 8 warps per CTA, 1 batch per warp
constexpr int WARPS_PER_CTA = THREADS / 32;

__global__ __launch_bounds__(THREADS)
void kabsch_rmsd_warp_kernel(const float* __restrict__ inp,
                             const float* __restrict__ tgt,
                             const int*   __restrict__ lens,
                             float*       __restrict__ out)
{
    const int warp = threadIdx.x >> 5;
    const int lane = threadIdx.x & 31;
    const int b = blockIdx.x * WARPS_PER_CTA + warp;   // one batch per warp
    if (b >= B_BATCH) return;

    const int n = lens[b] + 1;   // valid atoms: [0, n)
    const float4* __restrict__ x4 = reinterpret_cast<const float4*>(inp + (size_t)b * ROW);
    const float4* __restrict__ y4 = reinterpret_cast<const float4*>(tgt + (size_t)b * ROW);

    // acc layout: [0..2]=SX  [3..5]=SY  [6]=sum|x|^2  [7]=sum|y|^2  [8..16]=Sxy row-major
    float acc[17];
#pragma unroll
    for (int i = 0; i < 17; i++) acc[i] = 0.f;

    // each lane handles atom groups [lane*4, lane*4+4), stride 128 atoms
#pragma unroll 2
    for (int a0 = lane * 4; a0 < n; a0 += 32 * 4) {
        const int f = 3 * (a0 >> 2);     // float4 index of this 12-float group
        float4 xa = __ldcs(x4 + f), xb = __ldcs(x4 + f + 1), xc = __ldcs(x4 + f + 2);
        float4 ya = __ldcs(y4 + f), yb = __ldcs(y4 + f + 1), yc = __ldcs(y4 + f + 2);
        float xs[12] = {xa.x, xa.y, xa.z, xa.w, xb.x, xb.y, xb.z, xb.w, xc.x, xc.y, xc.z, xc.w};
        float ys[12] = {ya.x, ya.y, ya.z, ya.w, yb.x, yb.y, yb.z, yb.w, yc.x, yc.y, yc.z, yc.w};
#pragma unroll
        for (int j = 0; j < 4; j++) {
            if (a0 + j < n) {
                float x0 = xs[3*j], x1 = xs[3*j+1], x2 = xs[3*j+2];
                float y0 = ys[3*j], y1 = ys[3*j+1], y2 = ys[3*j+2];
                acc[0] += x0; acc[1] += x1; acc[2] += x2;
                acc[3] += y0; acc[4] += y1; acc[5] += y2;
                acc[6]  = fmaf(x0, x0, fmaf(x1, x1, fmaf(x2, x2, acc[6])));
                acc[7]  = fmaf(y0, y0, fmaf(y1, y1, fmaf(y2, y2, acc[7])));
                acc[8]  = fmaf(x0, y0, acc[8]);
                acc[9]  = fmaf(x0, y1, acc[9]);
                acc[10] = fmaf(x0, y2, acc[10]);
                acc[11] = fmaf(x1, y0, acc[11]);
                acc[12] = fmaf(x1, y1, acc[12]);
                acc[13] = fmaf(x1, y2, acc[13]);
                acc[14] = fmaf(x2, y0, acc[14]);
                acc[15] = fmaf(x2, y1, acc[15]);
                acc[16] = fmaf(x2, y2, acc[16]);
            }
        }
    }

    // warp-only tree reduction (no smem, no block barriers)
#pragma unroll
    for (int i = 0; i < 17; i++) {
#pragma unroll
        for (int o = 16; o > 0; o >>= 1)
            acc[i] += __shfl_down_sync(0xffffffffu, acc[i], o);
    }

    if (lane == 0) {
        const double nd = (double)n;
        double SX[3] = {acc[0], acc[1], acc[2]};
        double SY[3] = {acc[3], acc[4], acc[5]};
        double sxx = acc[6], syy = acc[7];

        double C[3][3];
#pragma unroll
        for (int i = 0; i < 3; i++)
#pragma unroll
            for (int j = 0; j < 3; j++)
                C[i][j] = (double)acc[8 + 3*i + j] - SX[i] * SY[j] / nd;

        double ssq = sxx - (SX[0]*SX[0] + SX[1]*SX[1] + SX[2]*SX[2]) / nd
                   + syy - (SY[0]*SY[0] + SY[1]*SY[1] + SY[2]*SY[2]) / nd;

        // M = C^T C (symmetric PSD); eigenvalues -> singular values of C
        double M[3][3];
#pragma unroll
        for (int i = 0; i < 3; i++)
#pragma unroll
            for (int j = 0; j < 3; j++) {
                double s = 0.0;
#pragma unroll
                for (int k = 0; k < 3; k++) s += C[k][i] * C[k][j];
                M[i][j] = s;
            }

        double q  = (M[0][0] + M[1][1] + M[2][2]) / 3.0;
        double p1 = M[0][1]*M[0][1] + M[0][2]*M[0][2] + M[1][2]*M[1][2];
        double a  = M[0][0] - q, bb = M[1][1] - q, c = M[2][2] - q;
        double p2 = a*a + bb*bb + c*c + 2.0 * p1;

        double e0, e1, e2;
        if (p2 <= 0.0) {
            e0 = e1 = e2 = q;
        } else {
            double p   = sqrt(p2 / 6.0);
            double inv = 1.0 / p;
            double B00 = a * inv, B11 = bb * inv, B22 = c * inv;
            double B01 = M[0][1] * inv, B02 = M[0][2] * inv, B12 = M[1][2] * inv;
            double detB = B00 * (B11*B22 - B12*B12)
                        - B01 * (B01*B22 - B12*B02)
                        + B02 * (B01*B12 - B11*B02);
            double r = 0.5 * detB;
            r = fmin(1.0, fmax(-1.0, r));
            double phi = acos(r) / 3.0;
            e0 = q + 2.0 * p * cos(phi);                        // largest
            e2 = q + 2.0 * p * cos(phi + 2.0943951023931953);   // smallest
            e1 = 3.0 * q - e0 - e2;                             // middle
        }

        double s0 = sqrt(fmax(e0, 0.0));
        double s1 = sqrt(fmax(e1, 0.0));
        double s2 = sqrt(fmax(e2, 0.0));

        double detC = C[0][0] * (C[1][1]*C[2][2] - C[1][2]*C[2][1])
                    - C[0][1] * (C[1][0]*C[2][2] - C[1][2]*C[2][0])
                    + C[0][2] * (C[1][0]*C[2][1] - C[1][1]*C[2][0]);
        double sgn = (detC > 0.0) ? 1.0 : ((detC < 0.0) ? -1.0 : 0.0);

        double tr  = s0 + s1 + sgn * s2;
        double msd = fmax(ssq - 2.0 * tr, 0.0) / nd;
        out[b] = (float)sqrt(msd + 1e-12);
    }
}

extern "C" void kernel_launch(void* const* d_in, const int* in_sizes, int n_in,
                              void* d_out, int out_size)
{
    const float* inp  = (const float*)d_in[0];
    const float* tgt  = (const float*)d_in[1];
    const int*   lens = (const int*)d_in[2];
    float*       out  = (float*)d_out;
    kabsch_rmsd_warp_kernel<<<B_BATCH / WARPS_PER_CTA, THREADS>>>(inp, tgt, lens, out);
}

// round 3
// speedup vs baseline: 4.9546x; 4.4643x over previous
#include <cuda_runtime.h>

constexpr int B_BATCH   = 4096;
constexpr int MAX_ATOMS = 2048;
constexpr int ROW       = 3 * MAX_ATOMS;   // 6144 floats per batch row
constexpr int THREADS   = 256;             // 8 warps per CTA, 1 batch per warp
constexpr int WARPS_PER_CTA = THREADS / 32;

__global__ __launch_bounds__(THREADS)
void kabsch_rmsd_warp_kernel(const float* __restrict__ inp,
                             const float* __restrict__ tgt,
                             const int*   __restrict__ lens,
                             float*       __restrict__ out)
{
    const int warp = threadIdx.x >> 5;
    const int lane = threadIdx.x & 31;
    const int b = blockIdx.x * WARPS_PER_CTA + warp;   // one batch per warp
    if (b >= B_BATCH) return;

    const int n = lens[b] + 1;   // valid atoms: [0, n)
    const float4* __restrict__ x4 = reinterpret_cast<const float4*>(inp + (size_t)b * ROW);
    const float4* __restrict__ y4 = reinterpret_cast<const float4*>(tgt + (size_t)b * ROW);

    // acc layout: [0..2]=SX  [3..5]=SY  [6]=sum|x|^2  [7]=sum|y|^2  [8..16]=Sxy row-major
    float acc[17];
#pragma unroll
    for (int i = 0; i < 17; i++) acc[i] = 0.f;

    // each lane handles atom groups [lane*4, lane*4+4), stride 128 atoms
#pragma unroll 2
    for (int a0 = lane * 4; a0 < n; a0 += 32 * 4) {
        const int f = 3 * (a0 >> 2);     // float4 index of this 12-float group
        float4 xa = __ldcs(x4 + f), xb = __ldcs(x4 + f + 1), xc = __ldcs(x4 + f + 2);
        float4 ya = __ldcs(y4 + f), yb = __ldcs(y4 + f + 1), yc = __ldcs(y4 + f + 2);
        float xs[12] = {xa.x, xa.y, xa.z, xa.w, xb.x, xb.y, xb.z, xb.w, xc.x, xc.y, xc.z, xc.w};
        float ys[12] = {ya.x, ya.y, ya.z, ya.w, yb.x, yb.y, yb.z, yb.w, yc.x, yc.y, yc.z, yc.w};
#pragma unroll
        for (int j = 0; j < 4; j++) {
            if (a0 + j < n) {
                float x0 = xs[3*j], x1 = xs[3*j+1], x2 = xs[3*j+2];
                float y0 = ys[3*j], y1 = ys[3*j+1], y2 = ys[3*j+2];
                acc[0] += x0; acc[1] += x1; acc[2] += x2;
                acc[3] += y0; acc[4] += y1; acc[5] += y2;
                acc[6]  = fmaf(x0, x0, fmaf(x1, x1, fmaf(x2, x2, acc[6])));
                acc[7]  = fmaf(y0, y0, fmaf(y1, y1, fmaf(y2, y2, acc[7])));
                acc[8]  = fmaf(x0, y0, acc[8]);
                acc[9]  = fmaf(x0, y1, acc[9]);
                acc[10] = fmaf(x0, y2, acc[10]);
                acc[11] = fmaf(x1, y0, acc[11]);
                acc[12] = fmaf(x1, y1, acc[12]);
                acc[13] = fmaf(x1, y2, acc[13]);
                acc[14] = fmaf(x2, y0, acc[14]);
                acc[15] = fmaf(x2, y1, acc[15]);
                acc[16] = fmaf(x2, y2, acc[16]);
            }
        }
    }

    // warp-only tree reduction (no smem, no block barriers)
#pragma unroll
    for (int i = 0; i < 17; i++) {
#pragma unroll
        for (int o = 16; o > 0; o >>= 1)
            acc[i] += __shfl_down_sync(0xffffffffu, acc[i], o);
    }

    if (lane == 0) {
        // ---------- fp32 epilogue (FP64 on sm_103a is ~100x slower; it was the bottleneck) ----------
        const float inv_n = __frcp_rn((float)n);

        float SX0 = acc[0], SX1 = acc[1], SX2 = acc[2];
        float SY0 = acc[3], SY1 = acc[4], SY2 = acc[5];
        float sxx = acc[6], syy = acc[7];

        // centered cross-covariance C = Sxy - SX*SY/n
        float C[3][3];
        const float SXs[3] = {SX0, SX1, SX2};
        const float SYs[3] = {SY0, SY1, SY2};
#pragma unroll
        for (int i = 0; i < 3; i++)
#pragma unroll
            for (int j = 0; j < 3; j++)
                C[i][j] = fmaf(-SXs[i] * inv_n, SYs[j], acc[8 + 3*i + j]);

        float ssq = sxx - (SX0*SX0 + SX1*SX1 + SX2*SX2) * inv_n
                  + syy - (SY0*SY0 + SY1*SY1 + SY2*SY2) * inv_n;

        // M = C^T C (symmetric PSD); eigenvalues = singular values^2 of C
        float M00 = C[0][0]*C[0][0] + C[1][0]*C[1][0] + C[2][0]*C[2][0];
        float M11 = C[0][1]*C[0][1] + C[1][1]*C[1][1] + C[2][1]*C[2][1];
        float M22 = C[0][2]*C[0][2] + C[1][2]*C[1][2] + C[2][2]*C[2][2];
        float M01 = C[0][0]*C[0][1] + C[1][0]*C[1][1] + C[2][0]*C[2][1];
        float M02 = C[0][0]*C[0][2] + C[1][0]*C[1][2] + C[2][0]*C[2][2];
        float M12 = C[0][1]*C[0][2] + C[1][1]*C[1][2] + C[2][1]*C[2][2];

        float q  = (M00 + M11 + M22) * (1.0f / 3.0f);
        float p1 = M01*M01 + M02*M02 + M12*M12;
        float a  = M00 - q, bb = M11 - q, c = M22 - q;
        float p2 = a*a + bb*bb + c*c + 2.0f * p1;

        float e0, e1, e2;
        if (p2 <= 0.0f) {
            e0 = e1 = e2 = q;
        } else {
            float p   = sqrtf(p2 * (1.0f / 6.0f));
            float inv = __frcp_rn(p);
            float B00 = a * inv, B11 = bb * inv, B22 = c * inv;
            float B01 = M01 * inv, B02 = M02 * inv, B12 = M12 * inv;
            float detB = B00 * fmaf(B11, B22, -B12*B12)
                       - B01 * fmaf(B01, B22, -B12*B02)
                       + B02 * fmaf(B01, B12, -B11*B02);
            float r = 0.5f * detB;
            r = fminf(1.0f, fmaxf(-1.0f, r));
            float phi = acosf(r) * (1.0f / 3.0f);
            e0 = fmaf(2.0f * p, cosf(phi), q);                           // largest
            e2 = fmaf(2.0f * p, cosf(phi + 2.0943951023931953f), q);     // smallest
            e1 = 3.0f * q - e0 - e2;                                     // middle
        }

        float s0 = sqrtf(fmaxf(e0, 0.0f));
        float s1 = sqrtf(fmaxf(e1, 0.0f));
        float s2 = sqrtf(fmaxf(e2, 0.0f));

        float detC = C[0][0] * fmaf(C[1][1], C[2][2], -C[1][2]*C[2][1])
                   - C[0][1] * fmaf(C[1][0], C[2][2], -C[1][2]*C[2][0])
                   + C[0][2] * fmaf(C[1][0], C[2][1], -C[1][1]*C[2][0]);
        float sgn = (detC > 0.0f) ? 1.0f : ((detC < 0.0f) ? -1.0f : 0.0f);

        float tr  = s0 + s1 + sgn * s2;
        float msd = fmaxf(fmaf(-2.0f, tr, ssq), 0.0f) * inv_n;
        out[b] = sqrtf(msd + 1e-12f);
    }
}

extern "C" void kernel_launch(void* const* d_in, const int* in_sizes, int n_in,
                              void* d_out, int out_size)
{
    const float* inp  = (const float*)d_in[0];
    const float* tgt  = (const float*)d_in[1];
    const int*   lens = (const int*)d_in[2];
    float*       out  = (float*)d_out;
    kabsch_rmsd_warp_kernel<<<B_BATCH / WARPS_PER_CTA, THREADS>>>(inp, tgt, lens, out);
}